// round 1
// baseline (speedup 1.0000x reference)
#include <cuda_runtime.h>

#define NN 100000
#define EE 1600000
#define EPSI 1e-12f

// ---------------- scratch (device globals; no allocation allowed) ----------------
__device__ float4 g_h4[NN * 16];    // L1: h1 = x@W1 (N x 64). L2 output phase: h2b (N x 32, first NN*8)
__device__ float4 g_agg4[NN * 16];  // aggregation buffer (N x 64 for L1, N x 32 for L2/L3)
__device__ float4 g_t4[NN * 8];     // h2pre = h1b @ W2 (N x 32)
__device__ float  g_degO[NN];
__device__ float  g_degI[NN];
__device__ float  g_degW[NN];
__device__ float  g_nw[EE];

// Vector reduction (no return) — sm_90+: one RED op carries 16 bytes.
__device__ __forceinline__ void red_add_f4(float4* p, float4 v) {
    asm volatile("red.global.add.v4.f32 [%0], {%1,%2,%3,%4};"
                 :: "l"(p), "f"(v.x), "f"(v.y), "f"(v.z), "f"(v.w)
                 : "memory");
}

// ---------------- zero kernels ----------------
__global__ void k_zero_deg() {
    int i = blockIdx.x * blockDim.x + threadIdx.x;
    if (i < NN) { g_degO[i] = 0.f; g_degI[i] = 0.f; g_degW[i] = 0.f; }
}
__global__ void k_zero_agg(int n4) {
    int i = blockIdx.x * blockDim.x + threadIdx.x;
    if (i < n4) g_agg4[i] = make_float4(0.f, 0.f, 0.f, 0.f);
}

// ---------------- degree + edge-norm ----------------
__global__ void k_deg(const int* __restrict__ src, const int* __restrict__ dst,
                      const float* __restrict__ w) {
    int e = blockIdx.x * blockDim.x + threadIdx.x;
    if (e < EE) {
        float wv = w[e];
        atomicAdd(&g_degO[src[e]], wv);
        atomicAdd(&g_degI[dst[e]], wv);
    }
}

// nw = w / sqrt(max(outdeg[src]*indeg[dst], eps)); also accumulate weighted in-degree of nw.
__global__ void k_nw(const int* __restrict__ src, const int* __restrict__ dst,
                     const float* __restrict__ w) {
    int e = blockIdx.x * blockDim.x + threadIdx.x;
    if (e < EE) {
        int s = src[e], d = dst[e];
        float nwv = w[e] * rsqrtf(fmaxf(g_degO[s] * g_degI[d], EPSI));
        g_nw[e] = nwv;
        atomicAdd(&g_degW[d], nwv);
    }
}

// ---------------- mm1: h1 = x @ W1  (N x 128) @ (128 x 64) ----------------
// 256 threads/block, 16 rows per tile; thread (r = t>>4, jg = t&15) -> row r, cols jg*4..jg*4+3
__global__ void k_mm1(const float* __restrict__ x, const float* __restrict__ W1) {
    __shared__ float ws[128 * 64];   // 32 KB
    __shared__ float xs[16 * 128];   // 8 KB
    int t = threadIdx.x;
    for (int i = t; i < 128 * 64; i += 256) ws[i] = W1[i];
    const float4* ws4 = (const float4*)ws;
    int jg = t & 15;
    int r  = t >> 4;
    for (int row0 = blockIdx.x * 16; row0 < NN; row0 += gridDim.x * 16) {
        __syncthreads();
        for (int i = t; i < 16 * 128; i += 256) {
            int rr = i >> 7, kk = i & 127;
            int row = row0 + rr;
            xs[i] = (row < NN) ? x[row * 128 + kk] : 0.f;
        }
        __syncthreads();
        float4 acc = make_float4(0.f, 0.f, 0.f, 0.f);
        #pragma unroll 8
        for (int k = 0; k < 128; k++) {
            float  xv = xs[r * 128 + k];
            float4 wv = ws4[k * 16 + jg];
            acc.x += xv * wv.x; acc.y += xv * wv.y;
            acc.z += xv * wv.z; acc.w += xv * wv.w;
        }
        int row = row0 + r;
        if (row < NN) g_h4[row * 16 + jg] = acc;
    }
}

// ---------------- scatter: agg[dst] += h[src] * nw ----------------
__global__ void k_scatter64(const int* __restrict__ src, const int* __restrict__ dst) {
    int i = blockIdx.x * blockDim.x + threadIdx.x;     // EE*16 = 25.6M
    if (i < EE * 16) {
        int e = i >> 4, c = i & 15;
        int s = src[e], d = dst[e];
        float nwv = g_nw[e];
        float4 hv = g_h4[s * 16 + c];
        red_add_f4(&g_agg4[d * 16 + c],
                   make_float4(hv.x * nwv, hv.y * nwv, hv.z * nwv, hv.w * nwv));
    }
}

// useT=1: read h from g_t4 (h2pre); useT=0: read from g_h4 (h2b, 32-wide)
__global__ void k_scatter32(const int* __restrict__ src, const int* __restrict__ dst, int useT) {
    int i = blockIdx.x * blockDim.x + threadIdx.x;     // EE*8 = 12.8M
    if (i < EE * 8) {
        int e = i >> 3, c = i & 7;
        int s = src[e], d = dst[e];
        float nwv = g_nw[e];
        const float4* hin = useT ? g_t4 : g_h4;
        float4 hv = hin[s * 8 + c];
        red_add_f4(&g_agg4[d * 8 + c],
                   make_float4(hv.x * nwv, hv.y * nwv, hv.z * nwv, hv.w * nwv));
    }
}

// ---------------- finalize L1 + transform L2: t = ((agg1/deg1)+b1) @ W2 ----------------
// 256 threads, 8 rows/tile; thread (r = t>>5, j = t&31)
__global__ void k_fin1mm2(const float* __restrict__ W2, const float* __restrict__ b1) {
    __shared__ float ws[64 * 32];    // 8 KB
    __shared__ float ts[8 * 64];
    __shared__ float b1s[64];
    __shared__ float invs[8];
    int t = threadIdx.x;
    for (int i = t; i < 64 * 32; i += 256) ws[i] = W2[i];
    if (t < 64) b1s[t] = b1[t];
    int r = t >> 5, j = t & 31;
    const float* agg = (const float*)g_agg4;
    for (int row0 = blockIdx.x * 8; row0 < NN; row0 += gridDim.x * 8) {
        __syncthreads();
        if (t < 8) {
            int row = row0 + t;
            invs[t] = (row < NN) ? (1.f / fmaxf(g_degW[row], EPSI)) : 0.f;
        }
        for (int i = t; i < 8 * 64; i += 256) {
            int rr = i >> 6, kk = i & 63;
            int row = row0 + rr;
            ts[i] = (row < NN) ? agg[row * 64 + kk] : 0.f;
        }
        __syncthreads();
        float inv = invs[r];
        float acc = 0.f;
        #pragma unroll
        for (int k = 0; k < 64; k++) {
            float v = ts[r * 64 + k] * inv + b1s[k];
            acc += v * ws[k * 32 + j];
        }
        int row = row0 + r;
        if (row < NN) ((float*)g_t4)[row * 32 + j] = acc;
    }
}

// ---------------- finalize L2: h2b = agg2/deg2 + b2 ----------------
__global__ void k_fin2(const float* __restrict__ b2) {
    int i = blockIdx.x * blockDim.x + threadIdx.x;     // NN*32
    if (i < NN * 32) {
        int row = i >> 5, j = i & 31;
        float inv = 1.f / fmaxf(g_degW[row], EPSI);
        ((float*)g_h4)[i] = ((const float*)g_agg4)[i] * inv + b2[j];
    }
}

// ---------------- finalize L3: out = (agg3 @ W3)/deg3 + b3 ----------------
__global__ void k_fin3(const float* __restrict__ W3, const float* __restrict__ b3,
                       float* __restrict__ out) {
    __shared__ float ws[32 * 32];    // 4 KB
    __shared__ float ts[8 * 32];
    __shared__ float b3s[32];
    __shared__ float invs[8];
    int t = threadIdx.x;
    for (int i = t; i < 32 * 32; i += 256) ws[i] = W3[i];
    if (t < 32) b3s[t] = b3[t];
    int r = t >> 5, j = t & 31;
    const float* agg = (const float*)g_agg4;
    for (int row0 = blockIdx.x * 8; row0 < NN; row0 += gridDim.x * 8) {
        __syncthreads();
        if (t < 8) {
            int row = row0 + t;
            invs[t] = (row < NN) ? (1.f / fmaxf(g_degW[row], EPSI)) : 0.f;
        }
        for (int i = t; i < 8 * 32; i += 256) {
            int rr = i >> 5, kk = i & 31;
            int row = row0 + rr;
            ts[i] = (row < NN) ? agg[row * 32 + kk] : 0.f;
        }
        __syncthreads();
        float acc = 0.f;
        #pragma unroll
        for (int k = 0; k < 32; k++)
            acc += ts[r * 32 + k] * ws[k * 32 + j];
        int row = row0 + r;
        if (row < NN) out[row * 32 + j] = acc * invs[r] + b3s[j];
    }
}

// ---------------- launch ----------------
extern "C" void kernel_launch(void* const* d_in, const int* in_sizes, int n_in,
                              void* d_out, int out_size) {
    const float* x    = (const float*)d_in[0];
    const int*   src1 = (const int*)  d_in[1];
    const int*   dst1 = (const int*)  d_in[2];
    const float* w1   = (const float*)d_in[3];
    const int*   src2 = (const int*)  d_in[4];
    const int*   dst2 = (const int*)  d_in[5];
    const float* w2   = (const float*)d_in[6];
    const int*   src3 = (const int*)  d_in[7];
    const int*   dst3 = (const int*)  d_in[8];
    const float* w3   = (const float*)d_in[9];
    const float* W1   = (const float*)d_in[10];
    const float* b1   = (const float*)d_in[11];
    const float* W2   = (const float*)d_in[12];
    const float* b2   = (const float*)d_in[13];
    const float* W3   = (const float*)d_in[14];
    const float* b3   = (const float*)d_in[15];
    float* out = (float*)d_out;

    const int TB = 256;
    const int gE = (EE + TB - 1) / TB;           // 6250
    const int gN = (NN + TB - 1) / TB;           // 391

    // ---------- Layer 1 ----------
    k_zero_deg<<<gN, TB>>>();
    k_zero_agg<<<(NN * 16 + TB - 1) / TB, TB>>>(NN * 16);
    k_deg<<<gE, TB>>>(src1, dst1, w1);
    k_nw<<<gE, TB>>>(src1, dst1, w1);
    k_mm1<<<(NN + 15) / 16, TB>>>(x, W1);
    k_scatter64<<<(EE * 16 + TB - 1) / TB, TB>>>(src1, dst1);
    k_fin1mm2<<<(NN + 7) / 8, TB>>>(W2, b1);

    // ---------- Layer 2 ----------
    k_zero_deg<<<gN, TB>>>();
    k_zero_agg<<<(NN * 8 + TB - 1) / TB, TB>>>(NN * 8);
    k_deg<<<gE, TB>>>(src2, dst2, w2);
    k_nw<<<gE, TB>>>(src2, dst2, w2);
    k_scatter32<<<(EE * 8 + TB - 1) / TB, TB>>>(src2, dst2, 1);
    k_fin2<<<(NN * 32 + TB - 1) / TB, TB>>>(b2);

    // ---------- Layer 3 ----------
    k_zero_deg<<<gN, TB>>>();
    k_zero_agg<<<(NN * 8 + TB - 1) / TB, TB>>>(NN * 8);
    k_deg<<<gE, TB>>>(src3, dst3, w3);
    k_nw<<<gE, TB>>>(src3, dst3, w3);
    k_scatter32<<<(EE * 8 + TB - 1) / TB, TB>>>(src3, dst3, 0);
    k_fin3<<<(NN + 7) / 8, TB>>>(W3, b3, out);
}

// round 3
// speedup vs baseline: 1.1435x; 1.1435x over previous
#include <cuda_runtime.h>

#define NN 100000
#define EE 1600000
#define EPSI 1e-12f
#define SCAN_B 512
#define NBLK ((NN + SCAN_B - 1) / SCAN_B)   // 196

// ---------------- scratch (device globals; no allocation allowed) ----------------
__device__ float4 g_h4[NN * 16];    // mm1 out h1 (N x 64); later h2b (N x 32)
__device__ float4 g_agg4[NN * 16];  // h1b (N x 64); later aggnorm3 (N x 32)
__device__ float4 g_t4[NN * 8];     // h2pre (N x 32)
__device__ float  g_degO[NN];
__device__ float  g_degI[NN];
__device__ int    g_cnt[NN];
__device__ int    g_ptr[NN + 1];
__device__ int    g_cur[NN];
__device__ int    g_psum[NBLK];
__device__ int    g_psumx[NBLK];
__device__ int2   g_csr[EE];        // (src, __float_as_int(nw)) sorted by dst

// ---------------- zero ----------------
__global__ void k_zero() {
    int i = blockIdx.x * blockDim.x + threadIdx.x;
    if (i < NN) { g_degO[i] = 0.f; g_degI[i] = 0.f; g_cnt[i] = 0; }
}

// ---------------- degrees + dst histogram ----------------
__global__ void k_deg(const int* __restrict__ src, const int* __restrict__ dst,
                      const float* __restrict__ w) {
    int e = blockIdx.x * blockDim.x + threadIdx.x;
    if (e < EE) {
        float wv = w[e];
        int d = dst[e];
        atomicAdd(&g_degO[src[e]], wv);
        atomicAdd(&g_degI[d], wv);
        atomicAdd(&g_cnt[d], 1);
    }
}

// ---------------- scan: cnt -> exclusive prefix (ptr) ----------------
__global__ void k_scan1() {
    __shared__ int s[SCAN_B];
    int t = threadIdx.x;
    int i = blockIdx.x * SCAN_B + t;
    s[t] = (i < NN) ? g_cnt[i] : 0;
    __syncthreads();
    for (int off = SCAN_B / 2; off > 0; off >>= 1) {
        if (t < off) s[t] += s[t + off];
        __syncthreads();
    }
    if (t == 0) g_psum[blockIdx.x] = s[0];
}

__global__ void k_scan2() {
    __shared__ int s[256];
    int t = threadIdx.x;
    int v = (t < NBLK) ? g_psum[t] : 0;
    s[t] = v;
    __syncthreads();
    for (int off = 1; off < 256; off <<= 1) {
        int x = (t >= off) ? s[t - off] : 0;
        __syncthreads();
        s[t] += x;
        __syncthreads();
    }
    if (t < NBLK) g_psumx[t] = s[t] - v;   // exclusive
}

__global__ void k_scan3() {
    __shared__ int s[SCAN_B];
    int t = threadIdx.x;
    int i = blockIdx.x * SCAN_B + t;
    int v = (i < NN) ? g_cnt[i] : 0;
    s[t] = v;
    __syncthreads();
    for (int off = 1; off < SCAN_B; off <<= 1) {
        int x = (t >= off) ? s[t - off] : 0;
        __syncthreads();
        s[t] += x;
        __syncthreads();
    }
    int excl = s[t] - v + g_psumx[blockIdx.x];
    if (i < NN) { g_ptr[i] = excl; g_cur[i] = excl; }
    if (i == NN - 1) g_ptr[NN] = excl + v;   // == EE
}

// ---------------- fill CSR: compute nw inline, bucket by dst ----------------
__global__ void k_fill(const int* __restrict__ src, const int* __restrict__ dst,
                       const float* __restrict__ w) {
    int e = blockIdx.x * blockDim.x + threadIdx.x;
    if (e < EE) {
        int s = src[e], d = dst[e];
        float nwv = w[e] * rsqrtf(fmaxf(g_degO[s] * g_degI[d], EPSI));
        int pos = atomicAdd(&g_cur[d], 1);
        g_csr[pos] = make_int2(s, __float_as_int(nwv));
    }
}

// ---------------- mm1: h1 = x @ W1  (N x 128) @ (128 x 64) -> g_h4 ----------------
__global__ void k_mm1(const float* __restrict__ x, const float* __restrict__ W1) {
    __shared__ float ws[128 * 64];
    __shared__ float xs[16 * 128];
    int t = threadIdx.x;
    for (int i = t; i < 128 * 64; i += 256) ws[i] = W1[i];
    const float4* ws4 = (const float4*)ws;
    int jg = t & 15;
    int r  = t >> 4;
    for (int row0 = blockIdx.x * 16; row0 < NN; row0 += gridDim.x * 16) {
        __syncthreads();
        for (int i = t; i < 16 * 128; i += 256) {
            int rr = i >> 7, kk = i & 127;
            int row = row0 + rr;
            xs[i] = (row < NN) ? x[row * 128 + kk] : 0.f;
        }
        __syncthreads();
        float4 acc = make_float4(0.f, 0.f, 0.f, 0.f);
        #pragma unroll 8
        for (int k = 0; k < 128; k++) {
            float  xv = xs[r * 128 + k];
            float4 wv = ws4[k * 16 + jg];
            acc.x += xv * wv.x; acc.y += xv * wv.y;
            acc.z += xv * wv.z; acc.w += xv * wv.w;
        }
        int row = row0 + r;
        if (row < NN) g_h4[row * 16 + jg] = acc;
    }
}

// ---------------- pull aggregation, 64-wide (layer 1): h1b = agg/deg + b1 -> g_agg4 ----
// 256 threads, 16 rows/block, 16 lanes/row (float4 each)
__global__ void k_pull64(const float* __restrict__ b1) {
    int t = threadIdx.x;
    int lr = t & 15;
    int row = blockIdx.x * 16 + (t >> 4);
    if (row >= NN) return;
    int beg = g_ptr[row], end = g_ptr[row + 1];
    float4 acc = make_float4(0.f, 0.f, 0.f, 0.f);
    float dw = 0.f;
    int j = beg;
    for (; j + 4 <= end; j += 4) {
        int2 e0 = __ldcs(&g_csr[j]);
        int2 e1 = __ldcs(&g_csr[j + 1]);
        int2 e2 = __ldcs(&g_csr[j + 2]);
        int2 e3 = __ldcs(&g_csr[j + 3]);
        float n0 = __int_as_float(e0.y), n1 = __int_as_float(e1.y);
        float n2 = __int_as_float(e2.y), n3 = __int_as_float(e3.y);
        float4 h0 = g_h4[e0.x * 16 + lr];
        float4 h1 = g_h4[e1.x * 16 + lr];
        float4 h2 = g_h4[e2.x * 16 + lr];
        float4 h3 = g_h4[e3.x * 16 + lr];
        acc.x += h0.x * n0 + h1.x * n1 + h2.x * n2 + h3.x * n3;
        acc.y += h0.y * n0 + h1.y * n1 + h2.y * n2 + h3.y * n3;
        acc.z += h0.z * n0 + h1.z * n1 + h2.z * n2 + h3.z * n3;
        acc.w += h0.w * n0 + h1.w * n1 + h2.w * n2 + h3.w * n3;
        dw += (n0 + n1) + (n2 + n3);
    }
    for (; j < end; j++) {
        int2 e0 = __ldcs(&g_csr[j]);
        float n0 = __int_as_float(e0.y);
        float4 h0 = g_h4[e0.x * 16 + lr];
        acc.x += h0.x * n0; acc.y += h0.y * n0;
        acc.z += h0.z * n0; acc.w += h0.w * n0;
        dw += n0;
    }
    float inv = 1.f / fmaxf(dw, EPSI);
    float4 bb = ((const float4*)b1)[lr];
    g_agg4[row * 16 + lr] = make_float4(acc.x * inv + bb.x, acc.y * inv + bb.y,
                                        acc.z * inv + bb.z, acc.w * inv + bb.w);
}

// ---------------- pull aggregation, 32-wide (layers 2 & 3) ----------------
// mode 1: in = g_t4 (h2pre), out = g_h4 = agg/deg + b2  (layer 2)
// mode 0: in = g_h4 (h2b),   out = g_agg4 = agg/deg     (layer 3, bias later)
__global__ void k_pull32(const float* __restrict__ b2, int mode) {
    int t = threadIdx.x;
    int lr = t & 7;
    int row = blockIdx.x * 32 + (t >> 3);
    if (row >= NN) return;
    const float4* hin = mode ? g_t4 : g_h4;
    int beg = g_ptr[row], end = g_ptr[row + 1];
    float4 acc = make_float4(0.f, 0.f, 0.f, 0.f);
    float dw = 0.f;
    int j = beg;
    for (; j + 4 <= end; j += 4) {
        int2 e0 = __ldcs(&g_csr[j]);
        int2 e1 = __ldcs(&g_csr[j + 1]);
        int2 e2 = __ldcs(&g_csr[j + 2]);
        int2 e3 = __ldcs(&g_csr[j + 3]);
        float n0 = __int_as_float(e0.y), n1 = __int_as_float(e1.y);
        float n2 = __int_as_float(e2.y), n3 = __int_as_float(e3.y);
        float4 h0 = hin[e0.x * 8 + lr];
        float4 h1 = hin[e1.x * 8 + lr];
        float4 h2 = hin[e2.x * 8 + lr];
        float4 h3 = hin[e3.x * 8 + lr];
        acc.x += h0.x * n0 + h1.x * n1 + h2.x * n2 + h3.x * n3;
        acc.y += h0.y * n0 + h1.y * n1 + h2.y * n2 + h3.y * n3;
        acc.z += h0.z * n0 + h1.z * n1 + h2.z * n2 + h3.z * n3;
        acc.w += h0.w * n0 + h1.w * n1 + h2.w * n2 + h3.w * n3;
        dw += (n0 + n1) + (n2 + n3);
    }
    for (; j < end; j++) {
        int2 e0 = __ldcs(&g_csr[j]);
        float n0 = __int_as_float(e0.y);
        float4 h0 = hin[e0.x * 8 + lr];
        acc.x += h0.x * n0; acc.y += h0.y * n0;
        acc.z += h0.z * n0; acc.w += h0.w * n0;
        dw += n0;
    }
    float inv = 1.f / fmaxf(dw, EPSI);
    if (mode) {
        float4 bb = ((const float4*)b2)[lr];
        g_h4[row * 8 + lr] = make_float4(acc.x * inv + bb.x, acc.y * inv + bb.y,
                                         acc.z * inv + bb.z, acc.w * inv + bb.w);
    } else {
        g_agg4[row * 8 + lr] = make_float4(acc.x * inv, acc.y * inv,
                                           acc.z * inv, acc.w * inv);
    }
}

// ---------------- mm2: h2pre = h1b @ W2  (N x 64) @ (64 x 32) -> g_t4 ----------------
__global__ void k_mm2(const float* __restrict__ W2) {
    __shared__ float ws[64 * 32];
    __shared__ float ts[8 * 64];
    int t = threadIdx.x;
    for (int i = t; i < 64 * 32; i += 256) ws[i] = W2[i];
    int r = t >> 5, j = t & 31;
    const float* hb = (const float*)g_agg4;
    for (int row0 = blockIdx.x * 8; row0 < NN; row0 += gridDim.x * 8) {
        __syncthreads();
        for (int i = t; i < 8 * 64; i += 256) {
            int rr = i >> 6, kk = i & 63;
            int row = row0 + rr;
            ts[i] = (row < NN) ? hb[row * 64 + kk] : 0.f;
        }
        __syncthreads();
        float acc = 0.f;
        #pragma unroll
        for (int k = 0; k < 64; k++)
            acc += ts[r * 64 + k] * ws[k * 32 + j];
        int row = row0 + r;
        if (row < NN) ((float*)g_t4)[row * 32 + j] = acc;
    }
}

// ---------------- fin3: out = aggnorm3 @ W3 + b3 ----------------
__global__ void k_fin3(const float* __restrict__ W3, const float* __restrict__ b3,
                       float* __restrict__ out) {
    __shared__ float ws[32 * 32];
    __shared__ float ts[8 * 32];
    __shared__ float b3s[32];
    int t = threadIdx.x;
    for (int i = t; i < 32 * 32; i += 256) ws[i] = W3[i];
    if (t < 32) b3s[t] = b3[t];
    int r = t >> 5, j = t & 31;
    const float* agg = (const float*)g_agg4;
    for (int row0 = blockIdx.x * 8; row0 < NN; row0 += gridDim.x * 8) {
        __syncthreads();
        for (int i = t; i < 8 * 32; i += 256) {
            int rr = i >> 5, kk = i & 31;
            int row = row0 + rr;
            ts[i] = (row < NN) ? agg[row * 32 + kk] : 0.f;
        }
        __syncthreads();
        float acc = 0.f;
        #pragma unroll
        for (int k = 0; k < 32; k++)
            acc += ts[r * 32 + k] * ws[k * 32 + j];
        int row = row0 + r;
        if (row < NN) out[row * 32 + j] = acc + b3s[j];
    }
}

// ---------------- launch ----------------
static inline void build_graph(const int* src, const int* dst, const float* w) {
    const int TB = 256;
    k_zero<<<(NN + TB - 1) / TB, TB>>>();
    k_deg<<<(EE + TB - 1) / TB, TB>>>(src, dst, w);
    k_scan1<<<NBLK, SCAN_B>>>();
    k_scan2<<<1, 256>>>();
    k_scan3<<<NBLK, SCAN_B>>>();
    k_fill<<<(EE + TB - 1) / TB, TB>>>(src, dst, w);
}

extern "C" void kernel_launch(void* const* d_in, const int* in_sizes, int n_in,
                              void* d_out, int out_size) {
    const float* x    = (const float*)d_in[0];
    const int*   src1 = (const int*)  d_in[1];
    const int*   dst1 = (const int*)  d_in[2];
    const float* w1   = (const float*)d_in[3];
    const int*   src2 = (const int*)  d_in[4];
    const int*   dst2 = (const int*)  d_in[5];
    const float* w2   = (const float*)d_in[6];
    const int*   src3 = (const int*)  d_in[7];
    const int*   dst3 = (const int*)  d_in[8];
    const float* w3   = (const float*)d_in[9];
    const float* W1   = (const float*)d_in[10];
    const float* b1   = (const float*)d_in[11];
    const float* W2   = (const float*)d_in[12];
    const float* b2   = (const float*)d_in[13];
    const float* W3   = (const float*)d_in[14];
    const float* b3   = (const float*)d_in[15];
    float* out = (float*)d_out;

    // ---------- Layer 1 ----------
    k_mm1<<<(NN + 15) / 16, 256>>>(x, W1);       // independent of graph build
    build_graph(src1, dst1, w1);
    k_pull64<<<(NN + 15) / 16, 256>>>(b1);       // -> g_agg4 (h1b)
    k_mm2<<<(NN + 7) / 8, 256>>>(W2);            // -> g_t4 (h2pre)

    // ---------- Layer 2 ----------
    build_graph(src2, dst2, w2);
    k_pull32<<<(NN + 31) / 32, 256>>>(b2, 1);    // g_t4 -> g_h4 (h2b)

    // ---------- Layer 3 ----------
    build_graph(src3, dst3, w3);
    k_pull32<<<(NN + 31) / 32, 256>>>(b2, 0);    // g_h4 -> g_agg4 (aggnorm3)
    k_fin3<<<(NN + 7) / 8, 256>>>(W3, b3, out);
}

// round 4
// speedup vs baseline: 1.2463x; 1.0899x over previous
#include <cuda_runtime.h>

#define NN 100000
#define EE 1600000
#define EPSI 1e-12f
#define SCAN_B 512
#define NBLK ((NN + SCAN_B - 1) / SCAN_B)   // 196

// ---------------- scratch (device globals; no allocation allowed) ----------------
__device__ float4 g_h4[NN * 16];        // h1 (N x 64); later h2b (N x 32)
__device__ float4 g_agg4[NN * 16];      // h1b (N x 64); later aggnorm3 (N x 32)
__device__ float4 g_t4[NN * 8];         // h2pre (N x 32)
__device__ float  g_degO[3 * NN];
__device__ float  g_degI[3 * NN];
__device__ int    g_cnt[3 * NN];
__device__ int    g_ptr[3 * (NN + 1)];
__device__ int    g_cur[3 * NN];
__device__ int    g_psum[3 * NBLK];
__device__ int    g_psumx[3 * NBLK];
__device__ int2   g_csr[3 * EE];        // (src, __float_as_int(w)) bucketed by dst

// ---------------- zero: all 3 graphs ----------------
__global__ void k_zero3() {
    int i = blockIdx.x * blockDim.x + threadIdx.x;
    if (i < 3 * NN) { g_degO[i] = 0.f; g_degI[i] = 0.f; g_cnt[i] = 0; }
}

// ---------------- degrees + dst histogram, 3 graphs at once ----------------
__global__ void k_deg3(const int* __restrict__ s1, const int* __restrict__ d1, const float* __restrict__ w1,
                       const int* __restrict__ s2, const int* __restrict__ d2, const float* __restrict__ w2,
                       const int* __restrict__ s3, const int* __restrict__ d3, const float* __restrict__ w3) {
    int g = blockIdx.y;
    const int*   src = (g == 0) ? s1 : (g == 1) ? s2 : s3;
    const int*   dst = (g == 0) ? d1 : (g == 1) ? d2 : d3;
    const float* w   = (g == 0) ? w1 : (g == 1) ? w2 : w3;
    int e = blockIdx.x * blockDim.x + threadIdx.x;
    if (e < EE) {
        float wv = w[e];
        int s = src[e], d = dst[e];
        int base = g * NN;
        atomicAdd(&g_degO[base + s], wv);
        atomicAdd(&g_degI[base + d], wv);
        atomicAdd(&g_cnt[base + d], 1);
    }
}

// ---------------- scans (per graph via blockIdx.y) ----------------
__global__ void k_scan1() {
    __shared__ int s[SCAN_B];
    int g = blockIdx.y;
    int t = threadIdx.x;
    int i = blockIdx.x * SCAN_B + t;
    s[t] = (i < NN) ? g_cnt[g * NN + i] : 0;
    __syncthreads();
    for (int off = SCAN_B / 2; off > 0; off >>= 1) {
        if (t < off) s[t] += s[t + off];
        __syncthreads();
    }
    if (t == 0) g_psum[g * NBLK + blockIdx.x] = s[0];
}

__global__ void k_scan2() {
    __shared__ int s[256];
    int g = blockIdx.y;
    int t = threadIdx.x;
    int v = (t < NBLK) ? g_psum[g * NBLK + t] : 0;
    s[t] = v;
    __syncthreads();
    for (int off = 1; off < 256; off <<= 1) {
        int x = (t >= off) ? s[t - off] : 0;
        __syncthreads();
        s[t] += x;
        __syncthreads();
    }
    if (t < NBLK) g_psumx[g * NBLK + t] = s[t] - v;   // exclusive
}

__global__ void k_scan3() {
    __shared__ int s[SCAN_B];
    int g = blockIdx.y;
    int t = threadIdx.x;
    int i = blockIdx.x * SCAN_B + t;
    int v = (i < NN) ? g_cnt[g * NN + i] : 0;
    s[t] = v;
    __syncthreads();
    for (int off = 1; off < SCAN_B; off <<= 1) {
        int x = (t >= off) ? s[t - off] : 0;
        __syncthreads();
        s[t] += x;
        __syncthreads();
    }
    int excl = s[t] - v + g_psumx[g * NBLK + blockIdx.x];
    if (i < NN) { g_ptr[g * (NN + 1) + i] = excl; g_cur[g * NN + i] = excl; }
    if (i == NN - 1) g_ptr[g * (NN + 1) + NN] = excl + v;   // == EE
}

// ---------------- fill CSR: (src, raw w), bucketed by dst, 3 graphs ----------------
__global__ void k_fill3(const int* __restrict__ s1, const int* __restrict__ d1, const float* __restrict__ w1,
                        const int* __restrict__ s2, const int* __restrict__ d2, const float* __restrict__ w2,
                        const int* __restrict__ s3, const int* __restrict__ d3, const float* __restrict__ w3) {
    int g = blockIdx.y;
    const int*   src = (g == 0) ? s1 : (g == 1) ? s2 : s3;
    const int*   dst = (g == 0) ? d1 : (g == 1) ? d2 : d3;
    const float* w   = (g == 0) ? w1 : (g == 1) ? w2 : w3;
    int e = blockIdx.x * blockDim.x + threadIdx.x;
    if (e < EE) {
        int s = src[e], d = dst[e];
        float wv = w[e];
        int pos = atomicAdd(&g_cur[g * NN + d], 1);
        g_csr[g * EE + pos] = make_int2(s, __float_as_int(wv));
    }
}

// ---------------- mm1: h1 = x @ W1  (N x 128)@(128 x 64) -> g_h4 ----------------
// 256 threads, 32 rows/tile, each thread: 2 rows x 4 cols
__global__ void k_mm1(const float* __restrict__ x, const float* __restrict__ W1) {
    __shared__ float ws[128 * 64];   // 32 KB
    __shared__ float xs[32 * 128];   // 16 KB
    int t = threadIdx.x;
    {
        const float4* W14 = (const float4*)W1;
        float4* ws4w = (float4*)ws;
        #pragma unroll
        for (int i = 0; i < 8; i++) ws4w[t + i * 256] = W14[t + i * 256];
    }
    const float4* ws4 = (const float4*)ws;
    int jg = t & 15;
    int r  = t >> 4;
    int row0 = blockIdx.x * 32;      // grid = 3125, exact
    {
        const float4* x4 = (const float4*)x;
        float4* xs4 = (float4*)xs;
        #pragma unroll
        for (int i = 0; i < 4; i++) {
            int idx = t + i * 256;   // 0..1023
            xs4[idx] = x4[row0 * 32 + idx];
        }
    }
    __syncthreads();
    float4 a0 = make_float4(0.f, 0.f, 0.f, 0.f);
    float4 a1 = make_float4(0.f, 0.f, 0.f, 0.f);
    #pragma unroll 4
    for (int k = 0; k < 128; k++) {
        float  x0 = xs[r * 128 + k];
        float  x1 = xs[(r + 16) * 128 + k];
        float4 wv = ws4[k * 16 + jg];
        a0.x += x0 * wv.x; a0.y += x0 * wv.y; a0.z += x0 * wv.z; a0.w += x0 * wv.w;
        a1.x += x1 * wv.x; a1.y += x1 * wv.y; a1.z += x1 * wv.z; a1.w += x1 * wv.w;
    }
    g_h4[(row0 + r) * 16 + jg]      = a0;
    g_h4[(row0 + r + 16) * 16 + jg] = a1;
}

// ---------------- pull 64-wide (layer 1, g=0): h1b = agg/deg + b1 -> g_agg4 ----------
// 256 threads, 16 rows/block, 16 lanes/row
__global__ void k_pull64(const float* __restrict__ b1) {
    int t = threadIdx.x;
    int lr = t & 15;
    int row = blockIdx.x * 16 + (t >> 4);
    if (row >= NN) return;
    int beg = g_ptr[row], end = g_ptr[row + 1];
    float indeg = g_degI[row];
    float4 acc = make_float4(0.f, 0.f, 0.f, 0.f);
    float dw = 0.f;
    int j = beg;
    for (; j + 4 <= end; j += 4) {
        int2 e0 = __ldcs(&g_csr[j]);
        int2 e1 = __ldcs(&g_csr[j + 1]);
        int2 e2 = __ldcs(&g_csr[j + 2]);
        int2 e3 = __ldcs(&g_csr[j + 3]);
        float o0 = g_degO[e0.x], o1 = g_degO[e1.x], o2 = g_degO[e2.x], o3 = g_degO[e3.x];
        float4 h0 = g_h4[e0.x * 16 + lr];
        float4 h1 = g_h4[e1.x * 16 + lr];
        float4 h2 = g_h4[e2.x * 16 + lr];
        float4 h3 = g_h4[e3.x * 16 + lr];
        float n0 = __int_as_float(e0.y) * rsqrtf(fmaxf(o0 * indeg, EPSI));
        float n1 = __int_as_float(e1.y) * rsqrtf(fmaxf(o1 * indeg, EPSI));
        float n2 = __int_as_float(e2.y) * rsqrtf(fmaxf(o2 * indeg, EPSI));
        float n3 = __int_as_float(e3.y) * rsqrtf(fmaxf(o3 * indeg, EPSI));
        acc.x += h0.x * n0 + h1.x * n1 + h2.x * n2 + h3.x * n3;
        acc.y += h0.y * n0 + h1.y * n1 + h2.y * n2 + h3.y * n3;
        acc.z += h0.z * n0 + h1.z * n1 + h2.z * n2 + h3.z * n3;
        acc.w += h0.w * n0 + h1.w * n1 + h2.w * n2 + h3.w * n3;
        dw += (n0 + n1) + (n2 + n3);
    }
    for (; j < end; j++) {
        int2 e0 = __ldcs(&g_csr[j]);
        float n0 = __int_as_float(e0.y) * rsqrtf(fmaxf(g_degO[e0.x] * indeg, EPSI));
        float4 h0 = g_h4[e0.x * 16 + lr];
        acc.x += h0.x * n0; acc.y += h0.y * n0;
        acc.z += h0.z * n0; acc.w += h0.w * n0;
        dw += n0;
    }
    float inv = 1.f / fmaxf(dw, EPSI);
    float4 bb = ((const float4*)b1)[lr];
    g_agg4[row * 16 + lr] = make_float4(acc.x * inv + bb.x, acc.y * inv + bb.y,
                                        acc.z * inv + bb.z, acc.w * inv + bb.w);
}

// ---------------- pull 32-wide (layers 2 & 3) ----------------
// mode 1 (g=1): in g_t4, out g_h4 = agg/deg + b2
// mode 0 (g=2): in g_h4, out g_agg4 = agg/deg
__global__ void k_pull32(const float* __restrict__ b2, int g, int mode) {
    int t = threadIdx.x;
    int lr = t & 7;
    int row = blockIdx.x * 32 + (t >> 3);
    if (row >= NN) return;
    const float4* hin = mode ? g_t4 : g_h4;
    const int2* csr = g_csr + g * EE;
    const float* degO = g_degO + g * NN;
    int beg = g_ptr[g * (NN + 1) + row], end = g_ptr[g * (NN + 1) + row + 1];
    float indeg = g_degI[g * NN + row];
    float4 acc = make_float4(0.f, 0.f, 0.f, 0.f);
    float dw = 0.f;
    int j = beg;
    for (; j + 4 <= end; j += 4) {
        int2 e0 = __ldcs(&csr[j]);
        int2 e1 = __ldcs(&csr[j + 1]);
        int2 e2 = __ldcs(&csr[j + 2]);
        int2 e3 = __ldcs(&csr[j + 3]);
        float o0 = degO[e0.x], o1 = degO[e1.x], o2 = degO[e2.x], o3 = degO[e3.x];
        float4 h0 = hin[e0.x * 8 + lr];
        float4 h1 = hin[e1.x * 8 + lr];
        float4 h2 = hin[e2.x * 8 + lr];
        float4 h3 = hin[e3.x * 8 + lr];
        float n0 = __int_as_float(e0.y) * rsqrtf(fmaxf(o0 * indeg, EPSI));
        float n1 = __int_as_float(e1.y) * rsqrtf(fmaxf(o1 * indeg, EPSI));
        float n2 = __int_as_float(e2.y) * rsqrtf(fmaxf(o2 * indeg, EPSI));
        float n3 = __int_as_float(e3.y) * rsqrtf(fmaxf(o3 * indeg, EPSI));
        acc.x += h0.x * n0 + h1.x * n1 + h2.x * n2 + h3.x * n3;
        acc.y += h0.y * n0 + h1.y * n1 + h2.y * n2 + h3.y * n3;
        acc.z += h0.z * n0 + h1.z * n1 + h2.z * n2 + h3.z * n3;
        acc.w += h0.w * n0 + h1.w * n1 + h2.w * n2 + h3.w * n3;
        dw += (n0 + n1) + (n2 + n3);
    }
    for (; j < end; j++) {
        int2 e0 = __ldcs(&csr[j]);
        float n0 = __int_as_float(e0.y) * rsqrtf(fmaxf(degO[e0.x] * indeg, EPSI));
        float4 h0 = hin[e0.x * 8 + lr];
        acc.x += h0.x * n0; acc.y += h0.y * n0;
        acc.z += h0.z * n0; acc.w += h0.w * n0;
        dw += n0;
    }
    float inv = 1.f / fmaxf(dw, EPSI);
    if (mode) {
        float4 bb = ((const float4*)b2)[lr];
        g_h4[row * 8 + lr] = make_float4(acc.x * inv + bb.x, acc.y * inv + bb.y,
                                         acc.z * inv + bb.z, acc.w * inv + bb.w);
    } else {
        g_agg4[row * 8 + lr] = make_float4(acc.x * inv, acc.y * inv,
                                           acc.z * inv, acc.w * inv);
    }
}

// ---------------- mm2: h2pre = h1b @ W2  (N x 64)@(64 x 32) -> g_t4 ----------------
__global__ void k_mm2(const float* __restrict__ W2) {
    __shared__ float ws[64 * 32];
    __shared__ float ts[8 * 64];
    int t = threadIdx.x;
    for (int i = t; i < 64 * 32; i += 256) ws[i] = W2[i];
    int r = t >> 5, j = t & 31;
    const float* hb = (const float*)g_agg4;
    for (int row0 = blockIdx.x * 8; row0 < NN; row0 += gridDim.x * 8) {
        __syncthreads();
        for (int i = t; i < 8 * 64; i += 256) {
            int rr = i >> 6, kk = i & 63;
            int row = row0 + rr;
            ts[i] = (row < NN) ? hb[row * 64 + kk] : 0.f;
        }
        __syncthreads();
        float acc = 0.f;
        #pragma unroll
        for (int k = 0; k < 64; k++)
            acc += ts[r * 64 + k] * ws[k * 32 + j];
        int row = row0 + r;
        if (row < NN) ((float*)g_t4)[row * 32 + j] = acc;
    }
}

// ---------------- fin3: out = aggnorm3 @ W3 + b3 ----------------
__global__ void k_fin3(const float* __restrict__ W3, const float* __restrict__ b3,
                       float* __restrict__ out) {
    __shared__ float ws[32 * 32];
    __shared__ float ts[8 * 32];
    __shared__ float b3s[32];
    int t = threadIdx.x;
    for (int i = t; i < 32 * 32; i += 256) ws[i] = W3[i];
    if (t < 32) b3s[t] = b3[t];
    int r = t >> 5, j = t & 31;
    const float* agg = (const float*)g_agg4;
    for (int row0 = blockIdx.x * 8; row0 < NN; row0 += gridDim.x * 8) {
        __syncthreads();
        for (int i = t; i < 8 * 32; i += 256) {
            int rr = i >> 5, kk = i & 31;
            int row = row0 + rr;
            ts[i] = (row < NN) ? agg[row * 32 + kk] : 0.f;
        }
        __syncthreads();
        float acc = 0.f;
        #pragma unroll
        for (int k = 0; k < 32; k++)
            acc += ts[r * 32 + k] * ws[k * 32 + j];
        int row = row0 + r;
        if (row < NN) out[row * 32 + j] = acc + b3s[j];
    }
}

// ---------------- launch ----------------
extern "C" void kernel_launch(void* const* d_in, const int* in_sizes, int n_in,
                              void* d_out, int out_size) {
    const float* x    = (const float*)d_in[0];
    const int*   src1 = (const int*)  d_in[1];
    const int*   dst1 = (const int*)  d_in[2];
    const float* w1   = (const float*)d_in[3];
    const int*   src2 = (const int*)  d_in[4];
    const int*   dst2 = (const int*)  d_in[5];
    const float* w2   = (const float*)d_in[6];
    const int*   src3 = (const int*)  d_in[7];
    const int*   dst3 = (const int*)  d_in[8];
    const float* w3   = (const float*)d_in[9];
    const float* W1   = (const float*)d_in[10];
    const float* b1   = (const float*)d_in[11];
    const float* W2   = (const float*)d_in[12];
    const float* b2   = (const float*)d_in[13];
    const float* W3   = (const float*)d_in[14];
    const float* b3   = (const float*)d_in[15];
    float* out = (float*)d_out;

    const int TB = 256;
    dim3 gE3((EE + TB - 1) / TB, 3);

    // Fused graph builds (all 3 graphs)
    k_zero3<<<(3 * NN + TB - 1) / TB, TB>>>();
    k_deg3<<<gE3, TB>>>(src1, dst1, w1, src2, dst2, w2, src3, dst3, w3);
    k_mm1<<<NN / 32, 256>>>(x, W1);              // independent; fills gap after deg3
    k_scan1<<<dim3(NBLK, 3), SCAN_B>>>();
    k_scan2<<<dim3(1, 3), 256>>>();
    k_scan3<<<dim3(NBLK, 3), SCAN_B>>>();
    k_fill3<<<gE3, TB>>>(src1, dst1, w1, src2, dst2, w2, src3, dst3, w3);

    // Dependent compute chain
    k_pull64<<<(NN + 15) / 16, 256>>>(b1);       // g=0: g_h4 -> g_agg4 (h1b)
    k_mm2<<<(NN + 7) / 8, 256>>>(W2);            // -> g_t4 (h2pre)
    k_pull32<<<(NN + 31) / 32, 256>>>(b2, 1, 1); // g=1: g_t4 -> g_h4 (h2b)
    k_pull32<<<(NN + 31) / 32, 256>>>(b2, 2, 0); // g=2: g_h4 -> g_agg4 (aggnorm3)
    k_fin3<<<(NN + 7) / 8, 256>>>(W3, b3, out);
}

// round 5
// speedup vs baseline: 1.4422x; 1.1571x over previous
#include <cuda_runtime.h>

#define NN 100000
#define EE 1600000
#define EPSI 1e-12f
#define SCAN_B 512
#define NBLK ((NN + SCAN_B - 1) / SCAN_B)   // 196

// ---------------- scratch (device globals; no allocation allowed) ----------------
__device__ float4 g_h4[NN * 16];        // h1 (N x 64); later h2b (N x 32)
__device__ float4 g_agg4[NN * 16];      // h1b (N x 64); later aggnorm3 (N x 32)
__device__ float4 g_t4[NN * 8];         // h2pre (N x 32)
__device__ float  g_degO[3 * NN];
__device__ float  g_sO[3 * NN];         // rsqrt(degO)
__device__ int    g_cnt[3 * NN];
__device__ int    g_ptr[3 * (NN + 1)];
__device__ int    g_cur[3 * NN];
__device__ int    g_psum[3 * NBLK];
__device__ int    g_psumx[3 * NBLK];
__device__ int2   g_csr[3 * EE];        // (src, __float_as_int(w*rsqrt(degO[src]))) bucketed by dst

// ---------------- zero: all 3 graphs ----------------
__global__ void k_zero3() {
    int i = blockIdx.x * blockDim.x + threadIdx.x;
    if (i < 3 * NN) { g_degO[i] = 0.f; g_cnt[i] = 0; }
}

// ---------------- degrees + dst histogram, 3 graphs at once ----------------
__global__ void k_deg3(const int* __restrict__ s1, const int* __restrict__ d1, const float* __restrict__ w1,
                       const int* __restrict__ s2, const int* __restrict__ d2, const float* __restrict__ w2,
                       const int* __restrict__ s3, const int* __restrict__ d3, const float* __restrict__ w3) {
    int g = blockIdx.y;
    const int*   src = (g == 0) ? s1 : (g == 1) ? s2 : s3;
    const int*   dst = (g == 0) ? d1 : (g == 1) ? d2 : d3;
    const float* w   = (g == 0) ? w1 : (g == 1) ? w2 : w3;
    int e = blockIdx.x * blockDim.x + threadIdx.x;
    if (e < EE) {
        int base = g * NN;
        atomicAdd(&g_degO[base + src[e]], w[e]);
        atomicAdd(&g_cnt[base + dst[e]], 1);
    }
}

// ---------------- sO = rsqrt(degO) ----------------
__global__ void k_rsq3() {
    int i = blockIdx.x * blockDim.x + threadIdx.x;
    if (i < 3 * NN) g_sO[i] = rsqrtf(fmaxf(g_degO[i], EPSI));
}

// ---------------- scans (per graph via blockIdx.y) ----------------
__global__ void k_scan1() {
    __shared__ int s[SCAN_B];
    int g = blockIdx.y;
    int t = threadIdx.x;
    int i = blockIdx.x * SCAN_B + t;
    s[t] = (i < NN) ? g_cnt[g * NN + i] : 0;
    __syncthreads();
    for (int off = SCAN_B / 2; off > 0; off >>= 1) {
        if (t < off) s[t] += s[t + off];
        __syncthreads();
    }
    if (t == 0) g_psum[g * NBLK + blockIdx.x] = s[0];
}

__global__ void k_scan2() {
    __shared__ int s[256];
    int g = blockIdx.y;
    int t = threadIdx.x;
    int v = (t < NBLK) ? g_psum[g * NBLK + t] : 0;
    s[t] = v;
    __syncthreads();
    for (int off = 1; off < 256; off <<= 1) {
        int x = (t >= off) ? s[t - off] : 0;
        __syncthreads();
        s[t] += x;
        __syncthreads();
    }
    if (t < NBLK) g_psumx[g * NBLK + t] = s[t] - v;   // exclusive
}

__global__ void k_scan3() {
    __shared__ int s[SCAN_B];
    int g = blockIdx.y;
    int t = threadIdx.x;
    int i = blockIdx.x * SCAN_B + t;
    int v = (i < NN) ? g_cnt[g * NN + i] : 0;
    s[t] = v;
    __syncthreads();
    for (int off = 1; off < SCAN_B; off <<= 1) {
        int x = (t >= off) ? s[t - off] : 0;
        __syncthreads();
        s[t] += x;
        __syncthreads();
    }
    int excl = s[t] - v + g_psumx[g * NBLK + blockIdx.x];
    if (i < NN) { g_ptr[g * (NN + 1) + i] = excl; g_cur[g * NN + i] = excl; }
    if (i == NN - 1) g_ptr[g * (NN + 1) + NN] = excl + v;   // == EE
}

// ---------------- fill CSR: (src, w*sO[src]), bucketed by dst, 3 graphs ----------------
__global__ void k_fill3(const int* __restrict__ s1, const int* __restrict__ d1, const float* __restrict__ w1,
                        const int* __restrict__ s2, const int* __restrict__ d2, const float* __restrict__ w2,
                        const int* __restrict__ s3, const int* __restrict__ d3, const float* __restrict__ w3) {
    int g = blockIdx.y;
    const int*   src = (g == 0) ? s1 : (g == 1) ? s2 : s3;
    const int*   dst = (g == 0) ? d1 : (g == 1) ? d2 : d3;
    const float* w   = (g == 0) ? w1 : (g == 1) ? w2 : w3;
    int e = blockIdx.x * blockDim.x + threadIdx.x;
    if (e < EE) {
        int s = src[e], d = dst[e];
        float ws = w[e] * g_sO[g * NN + s];
        int pos = atomicAdd(&g_cur[g * NN + d], 1);
        g_csr[g * EE + pos] = make_int2(s, __float_as_int(ws));
    }
}

// ---------------- mm1: h1 = x @ W1  (N x 128)@(128 x 64) -> g_h4 ----------------
__global__ void k_mm1(const float* __restrict__ x, const float* __restrict__ W1) {
    __shared__ float ws[128 * 64];   // 32 KB
    __shared__ float xs[32 * 128];   // 16 KB
    int t = threadIdx.x;
    {
        const float4* W14 = (const float4*)W1;
        float4* ws4w = (float4*)ws;
        #pragma unroll
        for (int i = 0; i < 8; i++) ws4w[t + i * 256] = W14[t + i * 256];
    }
    const float4* ws4 = (const float4*)ws;
    int jg = t & 15;
    int r  = t >> 4;
    int row0 = blockIdx.x * 32;      // grid = 3125, exact
    {
        const float4* x4 = (const float4*)x;
        float4* xs4 = (float4*)xs;
        #pragma unroll
        for (int i = 0; i < 4; i++) {
            int idx = t + i * 256;
            xs4[idx] = x4[row0 * 32 + idx];
        }
    }
    __syncthreads();
    float4 a0 = make_float4(0.f, 0.f, 0.f, 0.f);
    float4 a1 = make_float4(0.f, 0.f, 0.f, 0.f);
    #pragma unroll 4
    for (int k = 0; k < 128; k++) {
        float  x0 = xs[r * 128 + k];
        float  x1 = xs[(r + 16) * 128 + k];
        float4 wv = ws4[k * 16 + jg];
        a0.x += x0 * wv.x; a0.y += x0 * wv.y; a0.z += x0 * wv.z; a0.w += x0 * wv.w;
        a1.x += x1 * wv.x; a1.y += x1 * wv.y; a1.z += x1 * wv.z; a1.w += x1 * wv.w;
    }
    g_h4[(row0 + r) * 16 + jg]      = a0;
    g_h4[(row0 + r + 16) * 16 + jg] = a1;
}

// ---------------- pull 64-wide (layer 1, g=0): h1b = agg/dw + b1 -> g_agg4 ----------
// 256 threads, 16 rows/block, 16 lanes/row
__global__ void k_pull64(const float* __restrict__ b1) {
    int t = threadIdx.x;
    int lr = t & 15;
    int row = blockIdx.x * 16 + (t >> 4);
    if (row >= NN) return;
    int beg = g_ptr[row], end = g_ptr[row + 1];
    float4 acc = make_float4(0.f, 0.f, 0.f, 0.f);
    float dw = 0.f;
    int j = beg;
    for (; j + 4 <= end; j += 4) {
        int2 e0 = __ldcs(&g_csr[j]);
        int2 e1 = __ldcs(&g_csr[j + 1]);
        int2 e2 = __ldcs(&g_csr[j + 2]);
        int2 e3 = __ldcs(&g_csr[j + 3]);
        float n0 = __int_as_float(e0.y), n1 = __int_as_float(e1.y);
        float n2 = __int_as_float(e2.y), n3 = __int_as_float(e3.y);
        float4 h0 = g_h4[e0.x * 16 + lr];
        float4 h1 = g_h4[e1.x * 16 + lr];
        float4 h2 = g_h4[e2.x * 16 + lr];
        float4 h3 = g_h4[e3.x * 16 + lr];
        acc.x += h0.x * n0 + h1.x * n1 + h2.x * n2 + h3.x * n3;
        acc.y += h0.y * n0 + h1.y * n1 + h2.y * n2 + h3.y * n3;
        acc.z += h0.z * n0 + h1.z * n1 + h2.z * n2 + h3.z * n3;
        acc.w += h0.w * n0 + h1.w * n1 + h2.w * n2 + h3.w * n3;
        dw += (n0 + n1) + (n2 + n3);
    }
    for (; j < end; j++) {
        int2 e0 = __ldcs(&g_csr[j]);
        float n0 = __int_as_float(e0.y);
        float4 h0 = g_h4[e0.x * 16 + lr];
        acc.x += h0.x * n0; acc.y += h0.y * n0;
        acc.z += h0.z * n0; acc.w += h0.w * n0;
        dw += n0;
    }
    float inv = 1.f / fmaxf(dw, EPSI);
    float4 bb = ((const float4*)b1)[lr];
    g_agg4[row * 16 + lr] = make_float4(acc.x * inv + bb.x, acc.y * inv + bb.y,
                                        acc.z * inv + bb.z, acc.w * inv + bb.w);
}

// ---------------- pull 32-wide (layers 2 & 3) ----------------
// mode 1 (g=1): in g_t4, out g_h4 = agg/dw + b2
// mode 0 (g=2): in g_h4, out g_agg4 = agg/dw
__global__ void k_pull32(const float* __restrict__ b2, int g, int mode) {
    int t = threadIdx.x;
    int lr = t & 7;
    int row = blockIdx.x * 32 + (t >> 3);
    if (row >= NN) return;
    const float4* hin = mode ? g_t4 : g_h4;
    const int2* csr = g_csr + g * EE;
    int beg = g_ptr[g * (NN + 1) + row], end = g_ptr[g * (NN + 1) + row + 1];
    float4 acc = make_float4(0.f, 0.f, 0.f, 0.f);
    float dw = 0.f;
    int j = beg;
    for (; j + 4 <= end; j += 4) {
        int2 e0 = __ldcs(&csr[j]);
        int2 e1 = __ldcs(&csr[j + 1]);
        int2 e2 = __ldcs(&csr[j + 2]);
        int2 e3 = __ldcs(&csr[j + 3]);
        float n0 = __int_as_float(e0.y), n1 = __int_as_float(e1.y);
        float n2 = __int_as_float(e2.y), n3 = __int_as_float(e3.y);
        float4 h0 = hin[e0.x * 8 + lr];
        float4 h1 = hin[e1.x * 8 + lr];
        float4 h2 = hin[e2.x * 8 + lr];
        float4 h3 = hin[e3.x * 8 + lr];
        acc.x += h0.x * n0 + h1.x * n1 + h2.x * n2 + h3.x * n3;
        acc.y += h0.y * n0 + h1.y * n1 + h2.y * n2 + h3.y * n3;
        acc.z += h0.z * n0 + h1.z * n1 + h2.z * n2 + h3.z * n3;
        acc.w += h0.w * n0 + h1.w * n1 + h2.w * n2 + h3.w * n3;
        dw += (n0 + n1) + (n2 + n3);
    }
    for (; j < end; j++) {
        int2 e0 = __ldcs(&csr[j]);
        float n0 = __int_as_float(e0.y);
        float4 h0 = hin[e0.x * 8 + lr];
        acc.x += h0.x * n0; acc.y += h0.y * n0;
        acc.z += h0.z * n0; acc.w += h0.w * n0;
        dw += n0;
    }
    float inv = 1.f / fmaxf(dw, EPSI);
    if (mode) {
        float4 bb = ((const float4*)b2)[lr];
        g_h4[row * 8 + lr] = make_float4(acc.x * inv + bb.x, acc.y * inv + bb.y,
                                         acc.z * inv + bb.z, acc.w * inv + bb.w);
    } else {
        g_agg4[row * 8 + lr] = make_float4(acc.x * inv, acc.y * inv,
                                           acc.z * inv, acc.w * inv);
    }
}

// ---------------- mm2: h2pre = h1b @ W2  (N x 64)@(64 x 32) -> g_t4 ----------------
__global__ void k_mm2(const float* __restrict__ W2) {
    __shared__ float ws[64 * 32];
    __shared__ float ts[8 * 64];
    int t = threadIdx.x;
    for (int i = t; i < 64 * 32; i += 256) ws[i] = W2[i];
    int r = t >> 5, j = t & 31;
    const float* hb = (const float*)g_agg4;
    for (int row0 = blockIdx.x * 8; row0 < NN; row0 += gridDim.x * 8) {
        __syncthreads();
        for (int i = t; i < 8 * 64; i += 256) {
            int rr = i >> 6, kk = i & 63;
            int row = row0 + rr;
            ts[i] = (row < NN) ? hb[row * 64 + kk] : 0.f;
        }
        __syncthreads();
        float acc = 0.f;
        #pragma unroll
        for (int k = 0; k < 64; k++)
            acc += ts[r * 64 + k] * ws[k * 32 + j];
        int row = row0 + r;
        if (row < NN) ((float*)g_t4)[row * 32 + j] = acc;
    }
}

// ---------------- fin3: out = aggnorm3 @ W3 + b3 ----------------
__global__ void k_fin3(const float* __restrict__ W3, const float* __restrict__ b3,
                       float* __restrict__ out) {
    __shared__ float ws[32 * 32];
    __shared__ float ts[8 * 32];
    __shared__ float b3s[32];
    int t = threadIdx.x;
    for (int i = t; i < 32 * 32; i += 256) ws[i] = W3[i];
    if (t < 32) b3s[t] = b3[t];
    int r = t >> 5, j = t & 31;
    const float* agg = (const float*)g_agg4;
    for (int row0 = blockIdx.x * 8; row0 < NN; row0 += gridDim.x * 8) {
        __syncthreads();
        for (int i = t; i < 8 * 32; i += 256) {
            int rr = i >> 5, kk = i & 31;
            int row = row0 + rr;
            ts[i] = (row < NN) ? agg[row * 32 + kk] : 0.f;
        }
        __syncthreads();
        float acc = 0.f;
        #pragma unroll
        for (int k = 0; k < 32; k++)
            acc += ts[r * 32 + k] * ws[k * 32 + j];
        int row = row0 + r;
        if (row < NN) out[row * 32 + j] = acc + b3s[j];
    }
}

// ---------------- launch ----------------
extern "C" void kernel_launch(void* const* d_in, const int* in_sizes, int n_in,
                              void* d_out, int out_size) {
    const float* x    = (const float*)d_in[0];
    const int*   src1 = (const int*)  d_in[1];
    const int*   dst1 = (const int*)  d_in[2];
    const float* w1   = (const float*)d_in[3];
    const int*   src2 = (const int*)  d_in[4];
    const int*   dst2 = (const int*)  d_in[5];
    const float* w2   = (const float*)d_in[6];
    const int*   src3 = (const int*)  d_in[7];
    const int*   dst3 = (const int*)  d_in[8];
    const float* w3   = (const float*)d_in[9];
    const float* W1   = (const float*)d_in[10];
    const float* b1   = (const float*)d_in[11];
    const float* W2   = (const float*)d_in[12];
    const float* b2   = (const float*)d_in[13];
    const float* W3   = (const float*)d_in[14];
    const float* b3   = (const float*)d_in[15];
    float* out = (float*)d_out;

    const int TB = 256;
    dim3 gE3((EE + TB - 1) / TB, 3);

    // Fused graph builds (all 3 graphs)
    k_zero3<<<(3 * NN + TB - 1) / TB, TB>>>();
    k_deg3<<<gE3, TB>>>(src1, dst1, w1, src2, dst2, w2, src3, dst3, w3);
    k_mm1<<<NN / 32, 256>>>(x, W1);              // independent; fills gap after deg3
    k_rsq3<<<(3 * NN + TB - 1) / TB, TB>>>();
    k_scan1<<<dim3(NBLK, 3), SCAN_B>>>();
    k_scan2<<<dim3(1, 3), 256>>>();
    k_scan3<<<dim3(NBLK, 3), SCAN_B>>>();
    k_fill3<<<gE3, TB>>>(src1, dst1, w1, src2, dst2, w2, src3, dst3, w3);

    // Dependent compute chain
    k_pull64<<<(NN + 15) / 16, 256>>>(b1);       // g=0: g_h4 -> g_agg4 (h1b)
    k_mm2<<<(NN + 7) / 8, 256>>>(W2);            // -> g_t4 (h2pre)
    k_pull32<<<(NN + 31) / 32, 256>>>(b2, 1, 1); // g=1: g_t4 -> g_h4 (h2b)
    k_pull32<<<(NN + 31) / 32, 256>>>(b2, 2, 0); // g=2: g_h4 -> g_agg4 (aggnorm3)
    k_fin3<<<(NN + 7) / 8, 256>>>(W3, b3, out);
}

// round 6
// speedup vs baseline: 1.5135x; 1.0495x over previous
#include <cuda_runtime.h>

#define NN 100000
#define EE 1600000
#define EPSI 1e-12f
#define SCAN_B 512
#define NBLK ((NN + SCAN_B - 1) / SCAN_B)   // 196

// ---------------- scratch (device globals; no allocation allowed) ----------------
__device__ float4 g_h4[NN * 16];        // h1 (N x 64); later h2b (N x 32)
__device__ float4 g_t4[NN * 8];         // h2pre (N x 32)
__device__ float  g_degO[3 * NN];
__device__ float  g_sO[3 * NN];         // rsqrt(degO)
__device__ int    g_cnt[3 * NN];
__device__ int    g_ptr[3 * (NN + 1)];
__device__ int    g_cur[3 * NN];
__device__ int    g_psum[3 * NBLK];
__device__ int    g_psumx[3 * NBLK];
__device__ int2   g_csr[3 * EE];        // (src, __float_as_int(w*rsqrt(degO[src]))) bucketed by dst

// ---------------- zero: all 3 graphs ----------------
__global__ void k_zero3() {
    int i = blockIdx.x * blockDim.x + threadIdx.x;
    if (i < 3 * NN) { g_degO[i] = 0.f; g_cnt[i] = 0; }
}

// ---------------- degrees + dst histogram, 3 graphs at once ----------------
__global__ void k_deg3(const int* __restrict__ s1, const int* __restrict__ d1, const float* __restrict__ w1,
                       const int* __restrict__ s2, const int* __restrict__ d2, const float* __restrict__ w2,
                       const int* __restrict__ s3, const int* __restrict__ d3, const float* __restrict__ w3) {
    int g = blockIdx.y;
    const int*   src = (g == 0) ? s1 : (g == 1) ? s2 : s3;
    const int*   dst = (g == 0) ? d1 : (g == 1) ? d2 : d3;
    const float* w   = (g == 0) ? w1 : (g == 1) ? w2 : w3;
    int e = blockIdx.x * blockDim.x + threadIdx.x;
    if (e < EE) {
        int base = g * NN;
        atomicAdd(&g_degO[base + src[e]], w[e]);
        atomicAdd(&g_cnt[base + dst[e]], 1);
    }
}

// ---------------- sO = rsqrt(degO) ----------------
__global__ void k_rsq3() {
    int i = blockIdx.x * blockDim.x + threadIdx.x;
    if (i < 3 * NN) g_sO[i] = rsqrtf(fmaxf(g_degO[i], EPSI));
}

// ---------------- scans (per graph via blockIdx.y) ----------------
__global__ void k_scan1() {
    __shared__ int s[SCAN_B];
    int g = blockIdx.y;
    int t = threadIdx.x;
    int i = blockIdx.x * SCAN_B + t;
    s[t] = (i < NN) ? g_cnt[g * NN + i] : 0;
    __syncthreads();
    for (int off = SCAN_B / 2; off > 0; off >>= 1) {
        if (t < off) s[t] += s[t + off];
        __syncthreads();
    }
    if (t == 0) g_psum[g * NBLK + blockIdx.x] = s[0];
}

__global__ void k_scan2() {
    __shared__ int s[256];
    int g = blockIdx.y;
    int t = threadIdx.x;
    int v = (t < NBLK) ? g_psum[g * NBLK + t] : 0;
    s[t] = v;
    __syncthreads();
    for (int off = 1; off < 256; off <<= 1) {
        int x = (t >= off) ? s[t - off] : 0;
        __syncthreads();
        s[t] += x;
        __syncthreads();
    }
    if (t < NBLK) g_psumx[g * NBLK + t] = s[t] - v;   // exclusive
}

__global__ void k_scan3() {
    __shared__ int s[SCAN_B];
    int g = blockIdx.y;
    int t = threadIdx.x;
    int i = blockIdx.x * SCAN_B + t;
    int v = (i < NN) ? g_cnt[g * NN + i] : 0;
    s[t] = v;
    __syncthreads();
    for (int off = 1; off < SCAN_B; off <<= 1) {
        int x = (t >= off) ? s[t - off] : 0;
        __syncthreads();
        s[t] += x;
        __syncthreads();
    }
    int excl = s[t] - v + g_psumx[g * NBLK + blockIdx.x];
    if (i < NN) { g_ptr[g * (NN + 1) + i] = excl; g_cur[g * NN + i] = excl; }
    if (i == NN - 1) g_ptr[g * (NN + 1) + NN] = excl + v;   // == EE
}

// ---------------- fill CSR: (src, w*sO[src]), bucketed by dst, 3 graphs ----------------
__global__ void k_fill3(const int* __restrict__ s1, const int* __restrict__ d1, const float* __restrict__ w1,
                        const int* __restrict__ s2, const int* __restrict__ d2, const float* __restrict__ w2,
                        const int* __restrict__ s3, const int* __restrict__ d3, const float* __restrict__ w3) {
    int g = blockIdx.y;
    const int*   src = (g == 0) ? s1 : (g == 1) ? s2 : s3;
    const int*   dst = (g == 0) ? d1 : (g == 1) ? d2 : d3;
    const float* w   = (g == 0) ? w1 : (g == 1) ? w2 : w3;
    int e = blockIdx.x * blockDim.x + threadIdx.x;
    if (e < EE) {
        int s = src[e], d = dst[e];
        float ws = w[e] * g_sO[g * NN + s];
        int pos = atomicAdd(&g_cur[g * NN + d], 1);
        g_csr[g * EE + pos] = make_int2(s, __float_as_int(ws));
    }
}

// ---------------- mm1: h1 = x @ W1  (N x 128)@(128 x 64) -> g_h4 ----------------
__global__ void k_mm1(const float* __restrict__ x, const float* __restrict__ W1) {
    __shared__ float ws[128 * 64];   // 32 KB
    __shared__ float xs[32 * 128];   // 16 KB
    int t = threadIdx.x;
    {
        const float4* W14 = (const float4*)W1;
        float4* ws4w = (float4*)ws;
        #pragma unroll
        for (int i = 0; i < 8; i++) ws4w[t + i * 256] = W14[t + i * 256];
    }
    const float4* ws4 = (const float4*)ws;
    int jg = t & 15;
    int r  = t >> 4;
    int row0 = blockIdx.x * 32;      // grid = 3125, exact
    {
        const float4* x4 = (const float4*)x;
        float4* xs4 = (float4*)xs;
        #pragma unroll
        for (int i = 0; i < 4; i++) {
            int idx = t + i * 256;
            xs4[idx] = x4[row0 * 32 + idx];
        }
    }
    __syncthreads();
    float4 a0 = make_float4(0.f, 0.f, 0.f, 0.f);
    float4 a1 = make_float4(0.f, 0.f, 0.f, 0.f);
    #pragma unroll 4
    for (int k = 0; k < 128; k++) {
        float  x0 = xs[r * 128 + k];
        float  x1 = xs[(r + 16) * 128 + k];
        float4 wv = ws4[k * 16 + jg];
        a0.x += x0 * wv.x; a0.y += x0 * wv.y; a0.z += x0 * wv.z; a0.w += x0 * wv.w;
        a1.x += x1 * wv.x; a1.y += x1 * wv.y; a1.z += x1 * wv.z; a1.w += x1 * wv.w;
    }
    g_h4[(row0 + r) * 16 + jg]      = a0;
    g_h4[(row0 + r + 16) * 16 + jg] = a1;
}

// ---------------- fused pull64 (g=0) + mm2: h2pre = (agg1/dw + b1) @ W2 -> g_t4 ------
// 512 threads = 16 warps; warp w owns row blockIdx.x*16 + w.
// Lane = ep*16 + fl: ep in {0,1} edge-parallel, fl in 0..15 feature float4.
__global__ void __launch_bounds__(512) k_pull64mm2(const float* __restrict__ b1,
                                                   const float* __restrict__ W2) {
    __shared__ float hs[16 * 64];    // 4 KB block tile of h1b
    __shared__ float ws[64 * 32];    // 8 KB W2
    int t = threadIdx.x;
    ((float4*)ws)[t] = ((const float4*)W2)[t];   // 512 float4 = 2048 floats
    int w  = t >> 5;
    int ln = t & 31;
    int ep = ln >> 4;                // 0..1
    int fl = ln & 15;                // 0..15
    int row = blockIdx.x * 16 + w;   // exact: 6250*16 = 100000
    int beg = g_ptr[row], end = g_ptr[row + 1];
    float4 acc = make_float4(0.f, 0.f, 0.f, 0.f);
    float dw = 0.f;
    #pragma unroll 4
    for (int j = beg + ep; j < end; j += 2) {
        int2 e = __ldcs(&g_csr[j]);
        float n = __int_as_float(e.y);
        float4 h = g_h4[e.x * 16 + fl];
        acc.x += h.x * n; acc.y += h.y * n;
        acc.z += h.z * n; acc.w += h.w * n;
        dw += n;
    }
    // reduce across ep (xor 16)
    acc.x += __shfl_xor_sync(0xffffffffu, acc.x, 16);
    acc.y += __shfl_xor_sync(0xffffffffu, acc.y, 16);
    acc.z += __shfl_xor_sync(0xffffffffu, acc.z, 16);
    acc.w += __shfl_xor_sync(0xffffffffu, acc.w, 16);
    dw    += __shfl_xor_sync(0xffffffffu, dw, 16);
    if (ep == 0) {
        float inv = 1.f / fmaxf(dw, EPSI);
        float4 bb = ((const float4*)b1)[fl];
        ((float4*)hs)[w * 16 + fl] = make_float4(acc.x * inv + bb.x, acc.y * inv + bb.y,
                                                 acc.z * inv + bb.z, acc.w * inv + bb.w);
    }
    __syncthreads();
    // mm2: 16x64 @ 64x32 -> 16x32; thread -> (r = t>>5, c = t&31)
    int r = t >> 5, c = t & 31;
    float s = 0.f;
    #pragma unroll
    for (int k = 0; k < 64; k++)
        s += hs[r * 64 + k] * ws[k * 32 + c];
    ((float*)g_t4)[(blockIdx.x * 16 + r) * 32 + c] = s;
}

// ---------------- pull32 layer 2 (g=1): h2b = agg2/dw + b2 : g_t4 -> g_h4 -----------
// 512 threads = 16 warps, warp per row. Lane = ep*8 + fl, ep 0..3, fl 0..7.
__global__ void __launch_bounds__(512) k_pull32L2(const float* __restrict__ b2) {
    int t = threadIdx.x;
    int w  = t >> 5;
    int ln = t & 31;
    int ep = ln >> 3;                // 0..3
    int fl = ln & 7;                 // 0..7
    int row = blockIdx.x * 16 + w;
    const int2* csr = g_csr + 1 * EE;
    int beg = g_ptr[1 * (NN + 1) + row], end = g_ptr[1 * (NN + 1) + row + 1];
    float4 acc = make_float4(0.f, 0.f, 0.f, 0.f);
    float dw = 0.f;
    #pragma unroll 2
    for (int j = beg + ep; j < end; j += 4) {
        int2 e = __ldcs(&csr[j]);
        float n = __int_as_float(e.y);
        float4 h = g_t4[e.x * 8 + fl];
        acc.x += h.x * n; acc.y += h.y * n;
        acc.z += h.z * n; acc.w += h.w * n;
        dw += n;
    }
    acc.x += __shfl_xor_sync(0xffffffffu, acc.x, 8);
    acc.y += __shfl_xor_sync(0xffffffffu, acc.y, 8);
    acc.z += __shfl_xor_sync(0xffffffffu, acc.z, 8);
    acc.w += __shfl_xor_sync(0xffffffffu, acc.w, 8);
    dw    += __shfl_xor_sync(0xffffffffu, dw, 8);
    acc.x += __shfl_xor_sync(0xffffffffu, acc.x, 16);
    acc.y += __shfl_xor_sync(0xffffffffu, acc.y, 16);
    acc.z += __shfl_xor_sync(0xffffffffu, acc.z, 16);
    acc.w += __shfl_xor_sync(0xffffffffu, acc.w, 16);
    dw    += __shfl_xor_sync(0xffffffffu, dw, 16);
    if (ep == 0) {
        float inv = 1.f / fmaxf(dw, EPSI);
        float4 bb = ((const float4*)b2)[fl];
        g_h4[row * 8 + fl] = make_float4(acc.x * inv + bb.x, acc.y * inv + bb.y,
                                         acc.z * inv + bb.z, acc.w * inv + bb.w);
    }
}

// ---------------- fused pull32 layer 3 (g=2) + fin3: out = (agg3/dw) @ W3 + b3 ------
__global__ void __launch_bounds__(512) k_pull32fin3(const float* __restrict__ W3,
                                                    const float* __restrict__ b3,
                                                    float* __restrict__ out) {
    __shared__ float hs[16 * 32];    // 2 KB block tile of aggnorm3
    __shared__ float ws[32 * 32];    // 4 KB W3
    int t = threadIdx.x;
    if (t < 256) ((float4*)ws)[t] = ((const float4*)W3)[t];   // 256 float4 = 1024 floats
    int w  = t >> 5;
    int ln = t & 31;
    int ep = ln >> 3;
    int fl = ln & 7;
    int row = blockIdx.x * 16 + w;
    const int2* csr = g_csr + 2 * EE;
    int beg = g_ptr[2 * (NN + 1) + row], end = g_ptr[2 * (NN + 1) + row + 1];
    float4 acc = make_float4(0.f, 0.f, 0.f, 0.f);
    float dw = 0.f;
    #pragma unroll 2
    for (int j = beg + ep; j < end; j += 4) {
        int2 e = __ldcs(&csr[j]);
        float n = __int_as_float(e.y);
        float4 h = g_h4[e.x * 8 + fl];
        acc.x += h.x * n; acc.y += h.y * n;
        acc.z += h.z * n; acc.w += h.w * n;
        dw += n;
    }
    acc.x += __shfl_xor_sync(0xffffffffu, acc.x, 8);
    acc.y += __shfl_xor_sync(0xffffffffu, acc.y, 8);
    acc.z += __shfl_xor_sync(0xffffffffu, acc.z, 8);
    acc.w += __shfl_xor_sync(0xffffffffu, acc.w, 8);
    dw    += __shfl_xor_sync(0xffffffffu, dw, 8);
    acc.x += __shfl_xor_sync(0xffffffffu, acc.x, 16);
    acc.y += __shfl_xor_sync(0xffffffffu, acc.y, 16);
    acc.z += __shfl_xor_sync(0xffffffffu, acc.z, 16);
    acc.w += __shfl_xor_sync(0xffffffffu, acc.w, 16);
    dw    += __shfl_xor_sync(0xffffffffu, dw, 16);
    if (ep == 0) {
        float inv = 1.f / fmaxf(dw, EPSI);
        ((float4*)hs)[w * 8 + fl] = make_float4(acc.x * inv, acc.y * inv,
                                                acc.z * inv, acc.w * inv);
    }
    __syncthreads();
    // fin3: 16x32 @ 32x32 + b3; thread -> (r = t>>5, c = t&31)
    int r = t >> 5, c = t & 31;
    float s = 0.f;
    #pragma unroll
    for (int k = 0; k < 32; k++)
        s += hs[r * 32 + k] * ws[k * 32 + c];
    out[(blockIdx.x * 16 + r) * 32 + c] = s + b3[c];
}

// ---------------- launch ----------------
extern "C" void kernel_launch(void* const* d_in, const int* in_sizes, int n_in,
                              void* d_out, int out_size) {
    const float* x    = (const float*)d_in[0];
    const int*   src1 = (const int*)  d_in[1];
    const int*   dst1 = (const int*)  d_in[2];
    const float* w1   = (const float*)d_in[3];
    const int*   src2 = (const int*)  d_in[4];
    const int*   dst2 = (const int*)  d_in[5];
    const float* w2   = (const float*)d_in[6];
    const int*   src3 = (const int*)  d_in[7];
    const int*   dst3 = (const int*)  d_in[8];
    const float* w3   = (const float*)d_in[9];
    const float* W1   = (const float*)d_in[10];
    const float* b1   = (const float*)d_in[11];
    const float* W2   = (const float*)d_in[12];
    const float* b2   = (const float*)d_in[13];
    const float* W3   = (const float*)d_in[14];
    const float* b3   = (const float*)d_in[15];
    float* out = (float*)d_out;

    const int TB = 256;
    dim3 gE3((EE + TB - 1) / TB, 3);

    // Fused graph builds (all 3 graphs)
    k_zero3<<<(3 * NN + TB - 1) / TB, TB>>>();
    k_deg3<<<gE3, TB>>>(src1, dst1, w1, src2, dst2, w2, src3, dst3, w3);
    k_mm1<<<NN / 32, 256>>>(x, W1);              // independent; fills gap after deg3
    k_rsq3<<<(3 * NN + TB - 1) / TB, TB>>>();
    k_scan1<<<dim3(NBLK, 3), SCAN_B>>>();
    k_scan2<<<dim3(1, 3), 256>>>();
    k_scan3<<<dim3(NBLK, 3), SCAN_B>>>();
    k_fill3<<<gE3, TB>>>(src1, dst1, w1, src2, dst2, w2, src3, dst3, w3);

    // Dependent compute chain (fused)
    k_pull64mm2<<<NN / 16, 512>>>(b1, W2);       // g=0: g_h4 -> g_t4 (h2pre)
    k_pull32L2<<<NN / 16, 512>>>(b2);            // g=1: g_t4 -> g_h4 (h2b)
    k_pull32fin3<<<NN / 16, 512>>>(W3, b3, out); // g=2: g_h4 -> out
}